// round 1
// baseline (speedup 1.0000x reference)
#include <cuda_runtime.h>
#include <cstdint>
#include <cstddef>

#define D 128
#define NMAX 100000
#define GEMM_THREADS 512
#define TILE_ROWS 64
#define GEMM_SMEM (196608)   // 2*64KB weights + 2*32KB x tiles

// ---------------- static device scratch (no dynamic allocs allowed) -------
__device__ float g_agg[(size_t)NMAX * D];
__device__ float g_jump[(size_t)NMAX * D];
__device__ float g_h[(size_t)NMAX * D];
__device__ float g_deg[NMAX];

// ---------------- helpers -------------------------------------------------
__device__ __forceinline__ void red4(float* p, float4 v) {
    asm volatile("red.global.add.v4.f32 [%0], {%1,%2,%3,%4};"
                 :: "l"(p), "f"(v.x), "f"(v.y), "f"(v.z), "f"(v.w) : "memory");
}

__device__ __forceinline__ unsigned long long pack_dup(float x) {
    unsigned long long r;
    asm("mov.b64 %0, {%1, %1};" : "=l"(r) : "r"(__float_as_uint(x)));
    return r;
}

__device__ __forceinline__ void ffma2(unsigned long long& acc,
                                      unsigned long long a,
                                      unsigned long long b) {
    asm("fma.rn.f32x2 %0, %1, %2, %0;" : "+l"(acc) : "l"(a), "l"(b));
}

__device__ __forceinline__ void unpack2(unsigned long long v, float& lo, float& hi) {
    unsigned int l, h;
    asm("mov.b64 {%0, %1}, %2;" : "=r"(l), "=r"(h) : "l"(v));
    lo = __uint_as_float(l);
    hi = __uint_as_float(h);
}

__device__ __forceinline__ float tanh_fast(float x) {
    float y;
    asm("tanh.approx.f32 %0, %1;" : "=f"(y) : "f"(x));
    return y;
}

// ---------------- scatter: agg[dst] += x[src] * rel[etype], deg count -----
__global__ void scatter_kernel(const float* __restrict__ x,
                               const float* __restrict__ rel,
                               const int* __restrict__ ei,     // [2, E]
                               const int* __restrict__ etype,  // [E]
                               float* __restrict__ agg,
                               float* __restrict__ deg,        // null on layer 2
                               int E)
{
    int e = blockIdx.x * (blockDim.x >> 5) + (threadIdx.x >> 5);
    if (e >= E) return;
    int lane = threadIdx.x & 31;
    int s = __ldg(ei + e);
    int d = __ldg(ei + E + e);
    int t = __ldg(etype + e);
    float4 xv = *(const float4*)(x + (size_t)s * D + lane * 4);
    float4 rv = *(const float4*)(rel + (size_t)t * D + lane * 4);
    float4 m;
    m.x = xv.x * rv.x; m.y = xv.y * rv.y;
    m.z = xv.z * rv.z; m.w = xv.w * rv.w;
    red4(agg + (size_t)d * D + lane * 4, m);
    if (deg != nullptr && lane == 0)
        atomicAdd(deg + d, 1.0f);
}

// ---------------- jump: out[jdst] += w[e] * emb[jsrc] ---------------------
__global__ void jump_kernel(const float* __restrict__ emb,
                            const float* __restrict__ ew,
                            const int* __restrict__ ej,   // [2, EJ]
                            float* __restrict__ out,
                            int EJ)
{
    int e = blockIdx.x * (blockDim.x >> 5) + (threadIdx.x >> 5);
    if (e >= EJ) return;
    int lane = threadIdx.x & 31;
    int s = __ldg(ej + e);
    int d = __ldg(ej + EJ + e);
    float w = __ldg(ew + e);
    float4 xv = *(const float4*)(emb + (size_t)s * D + lane * 4);
    float4 m;
    m.x = xv.x * w; m.y = xv.y * w; m.z = xv.z * w; m.w = xv.w * w;
    red4(out + (size_t)d * D + lane * 4, m);
}

// ---------------- fused GEMM + epilogue -----------------------------------
// out[r] = xb[r] + res * tanh( (agg[r]/max(deg,1)) @ W + xb[r] @ Wl )
//          [ + jw * jump[r]  when jump != null ]
__global__ __launch_bounds__(GEMM_THREADS, 1)
void gemm_fused_kernel(const float* __restrict__ agg,
                       const float* __restrict__ deg,
                       const float* __restrict__ xb,
                       const float* __restrict__ W,
                       const float* __restrict__ Wl,
                       const float* __restrict__ res_p,
                       const float* __restrict__ jump,
                       const float* __restrict__ jw_p,
                       float* __restrict__ out,
                       int N)
{
    extern __shared__ float sm[];
    float* Ws  = sm;           // 128x128
    float* Wls = sm + 16384;   // 128x128
    float* xsa = sm + 32768;   // 64x128
    float* xsb = sm + 40960;   // 64x128

    const int t = threadIdx.x;

    // stage both weight matrices
    for (int i = t * 4; i < 16384; i += GEMM_THREADS * 4) {
        *(float4*)(Ws + i)  = *(const float4*)(W + i);
        *(float4*)(Wls + i) = *(const float4*)(Wl + i);
    }
    const float res = __ldg(res_p);
    const float jw  = jump ? __ldg(jw_p) : 0.0f;

    const int rg = t >> 4;       // 0..31
    const int cg = t & 15;       // 0..15
    const int cb = cg * 8;       // 8 output cols per thread

    for (int row0 = blockIdx.x * TILE_ROWS; row0 < N; row0 += gridDim.x * TILE_ROWS) {
        __syncthreads();
        // stage x tiles (agg scaled by 1/deg, xb raw)
        for (int i = t * 4; i < TILE_ROWS * D; i += GEMM_THREADS * 4) {
            int r = i >> 7;
            int row = row0 + r;
            float4 a, b;
            if (row < N) {
                float inv = 1.0f / fmaxf(__ldg(deg + row), 1.0f);
                a = *(const float4*)(agg + (size_t)row * D + (i & 127));
                a.x *= inv; a.y *= inv; a.z *= inv; a.w *= inv;
                b = *(const float4*)(xb + (size_t)row * D + (i & 127));
            } else {
                a = make_float4(0.f, 0.f, 0.f, 0.f);
                b = a;
            }
            *(float4*)(xsa + i) = a;
            *(float4*)(xsb + i) = b;
        }
        __syncthreads();

        unsigned long long acc[2][4];
        #pragma unroll
        for (int r = 0; r < 2; r++)
            #pragma unroll
            for (int j = 0; j < 4; j++) acc[r][j] = 0ull;

        const float* xa0 = xsa + rg * D;
        const float* xa1 = xsa + (rg + 32) * D;
        const float* xb0 = xsb + rg * D;
        const float* xb1 = xsb + (rg + 32) * D;

        #pragma unroll 4
        for (int k = 0; k < D; k++) {
            unsigned long long A0 = pack_dup(xa0[k]);
            unsigned long long A1 = pack_dup(xa1[k]);
            unsigned long long B0 = pack_dup(xb0[k]);
            unsigned long long B1 = pack_dup(xb1[k]);
            ulonglong2 w01 = *(const ulonglong2*)(Ws + k * D + cb);
            ulonglong2 w23 = *(const ulonglong2*)(Ws + k * D + cb + 4);
            ulonglong2 l01 = *(const ulonglong2*)(Wls + k * D + cb);
            ulonglong2 l23 = *(const ulonglong2*)(Wls + k * D + cb + 4);
            ffma2(acc[0][0], A0, w01.x); ffma2(acc[0][1], A0, w01.y);
            ffma2(acc[0][2], A0, w23.x); ffma2(acc[0][3], A0, w23.y);
            ffma2(acc[1][0], A1, w01.x); ffma2(acc[1][1], A1, w01.y);
            ffma2(acc[1][2], A1, w23.x); ffma2(acc[1][3], A1, w23.y);
            ffma2(acc[0][0], B0, l01.x); ffma2(acc[0][1], B0, l01.y);
            ffma2(acc[0][2], B0, l23.x); ffma2(acc[0][3], B0, l23.y);
            ffma2(acc[1][0], B1, l01.x); ffma2(acc[1][1], B1, l01.y);
            ffma2(acc[1][2], B1, l23.x); ffma2(acc[1][3], B1, l23.y);
        }

        #pragma unroll
        for (int rr = 0; rr < 2; rr++) {
            int row = row0 + rg + rr * 32;
            if (row >= N) continue;
            const float* xbr = rr ? xb1 : xb0;
            float o[8];
            #pragma unroll
            for (int j = 0; j < 4; j++)
                unpack2(acc[rr][j], o[2 * j], o[2 * j + 1]);
            #pragma unroll
            for (int j = 0; j < 8; j++) {
                float v = xbr[cb + j] + res * tanh_fast(o[j]);
                if (jump)
                    v += jw * __ldg(jump + (size_t)row * D + cb + j);
                o[j] = v;
            }
            *(float4*)(out + (size_t)row * D + cb)     = make_float4(o[0], o[1], o[2], o[3]);
            *(float4*)(out + (size_t)row * D + cb + 4) = make_float4(o[4], o[5], o[6], o[7]);
        }
    }
}

// ---------------- launcher ------------------------------------------------
extern "C" void kernel_launch(void* const* d_in, const int* in_sizes, int n_in,
                              void* d_out, int out_size)
{
    const float* emb    = (const float*)d_in[0];
    const float* change = (const float*)d_in[1];
    const float* W1     = (const float*)d_in[2];
    const float* Wl1    = (const float*)d_in[3];
    const float* rel1   = (const float*)d_in[4];
    const float* W2     = (const float*)d_in[5];
    const float* Wl2    = (const float*)d_in[6];
    const float* rel2   = (const float*)d_in[7];
    const float* res    = (const float*)d_in[8];
    const float* jw     = (const float*)d_in[9];
    const float* ewj    = (const float*)d_in[10];
    const int*   ei     = (const int*)d_in[11];
    const int*   et     = (const int*)d_in[12];
    const int*   ej     = (const int*)d_in[13];

    const int N  = in_sizes[0] / D;
    const int E  = in_sizes[12];
    const int EJ = in_sizes[10];

    float* out = (float*)d_out;

    float *agg, *jmp, *h, *deg;
    cudaGetSymbolAddress((void**)&agg, g_agg);
    cudaGetSymbolAddress((void**)&jmp, g_jump);
    cudaGetSymbolAddress((void**)&h,   g_h);
    cudaGetSymbolAddress((void**)&deg, g_deg);

    cudaFuncSetAttribute(gemm_fused_kernel,
                         cudaFuncAttributeMaxDynamicSharedMemorySize, GEMM_SMEM);

    const size_t nd = (size_t)N * D * sizeof(float);

    cudaMemsetAsync(agg, 0, nd);
    cudaMemsetAsync(jmp, 0, nd);
    cudaMemsetAsync(deg, 0, (size_t)N * sizeof(float));

    const int eb = (E + 7) / 8;
    const int jb = (EJ + 7) / 8;
    const int gblocks = 296;

    // layer 1 scatter (+ degree count) and jump scatter (independent)
    scatter_kernel<<<eb, 256>>>(emb, rel1, ei, et, agg, deg, E);
    jump_kernel<<<jb, 256>>>(emb, ewj, ej, jmp, EJ);

    // h = emb + res*tanh((agg/deg)@W1 + emb@Wl1)
    gemm_fused_kernel<<<gblocks, GEMM_THREADS, GEMM_SMEM>>>(
        agg, deg, emb, W1, Wl1, res, nullptr, nullptr, h, N);

    // layer 2 scatter
    cudaMemsetAsync(agg, 0, nd);
    scatter_kernel<<<eb, 256>>>(h, rel2, ei, et, agg, nullptr, E);

    // dchange = h + res*tanh((agg/deg)@W2 + h@Wl2) + jw*jump
    gemm_fused_kernel<<<gblocks, GEMM_THREADS, GEMM_SMEM>>>(
        agg, deg, h, W2, Wl2, res, jmp, jw, out + (size_t)N * D, N);

    // first output: change passthrough
    cudaMemcpyAsync(out, change, nd, cudaMemcpyDeviceToDevice);
}

// round 2
// speedup vs baseline: 1.5958x; 1.5958x over previous
#include <cuda_runtime.h>
#include <cstdint>
#include <cstddef>

#define D 128
#define NMAX 100000
#define GEMM_THREADS 512
#define TILE_ROWS 64
#define XT_STRIDE 65                       // transposed x tile, pad to kill bank conflicts
#define GEMM_SMEM ((16384 + 16384 + 128*XT_STRIDE*2) * 4)   // 197632 B

// ---------------- static device scratch (no dynamic allocs allowed) -------
__device__ float g_agg[(size_t)NMAX * D];
__device__ float g_jump[(size_t)NMAX * D];
__device__ float g_h[(size_t)NMAX * D];
__device__ float g_deg[NMAX];

// ---------------- helpers -------------------------------------------------
__device__ __forceinline__ void red4(float* p, float4 v) {
    asm volatile("red.global.add.v4.f32 [%0], {%1,%2,%3,%4};"
                 :: "l"(p), "f"(v.x), "f"(v.y), "f"(v.z), "f"(v.w) : "memory");
}

__device__ __forceinline__ unsigned long long pack_dup(float x) {
    unsigned long long r;
    asm("mov.b64 %0, {%1, %1};" : "=l"(r) : "r"(__float_as_uint(x)));
    return r;
}

__device__ __forceinline__ void ffma2(unsigned long long& acc,
                                      unsigned long long a,
                                      unsigned long long b) {
    asm("fma.rn.f32x2 %0, %1, %2, %0;" : "+l"(acc) : "l"(a), "l"(b));
}

__device__ __forceinline__ void unpack2(unsigned long long v, float& lo, float& hi) {
    unsigned int l, h;
    asm("mov.b64 {%0, %1}, %2;" : "=r"(l), "=r"(h) : "l"(v));
    lo = __uint_as_float(l);
    hi = __uint_as_float(h);
}

__device__ __forceinline__ float tanh_fast(float x) {
    float y;
    asm("tanh.approx.f32 %0, %1;" : "=f"(y) : "f"(x));
    return y;
}

// ---------------- scatter: agg[dst] += x[src] * rel[etype], deg count -----
__global__ void scatter_kernel(const float* __restrict__ x,
                               const float* __restrict__ rel,
                               const int* __restrict__ ei,     // [2, E]
                               const int* __restrict__ etype,  // [E]
                               float* __restrict__ agg,
                               float* __restrict__ deg,        // null on layer 2
                               int E)
{
    int e = blockIdx.x * (blockDim.x >> 5) + (threadIdx.x >> 5);
    if (e >= E) return;
    int lane = threadIdx.x & 31;
    int s = __ldg(ei + e);
    int d = __ldg(ei + E + e);
    int t = __ldg(etype + e);
    float4 xv = *(const float4*)(x + (size_t)s * D + lane * 4);
    float4 rv = *(const float4*)(rel + (size_t)t * D + lane * 4);
    float4 m;
    m.x = xv.x * rv.x; m.y = xv.y * rv.y;
    m.z = xv.z * rv.z; m.w = xv.w * rv.w;
    red4(agg + (size_t)d * D + lane * 4, m);
    if (deg != nullptr && lane == 0)
        atomicAdd(deg + d, 1.0f);
}

// ---------------- jump: out[jdst] += w[e] * emb[jsrc] ---------------------
__global__ void jump_kernel(const float* __restrict__ emb,
                            const float* __restrict__ ew,
                            const int* __restrict__ ej,   // [2, EJ]
                            float* __restrict__ out,
                            int EJ)
{
    int e = blockIdx.x * (blockDim.x >> 5) + (threadIdx.x >> 5);
    if (e >= EJ) return;
    int lane = threadIdx.x & 31;
    int s = __ldg(ej + e);
    int d = __ldg(ej + EJ + e);
    float w = __ldg(ew + e);
    float4 xv = *(const float4*)(emb + (size_t)s * D + lane * 4);
    float4 m;
    m.x = xv.x * w; m.y = xv.y * w; m.z = xv.z * w; m.w = xv.w * w;
    red4(out + (size_t)d * D + lane * 4, m);
}

// ---------------- fused GEMM + epilogue -----------------------------------
// out[r] = xb[r] + res * tanh( (agg[r]/max(deg,1)) @ W + xb[r] @ Wl )
//          [ + jw * jump[r]  when jump != null ]
//
// Warp layout: cg = t>>5 (column group, 8 cols), lane = row within tile.
// All lanes of a warp read the SAME weight address  -> smem broadcast (1 phase).
// x tiles stored TRANSPOSED with stride 65          -> conflict-free x reads.
__global__ __launch_bounds__(GEMM_THREADS, 1)
void gemm_fused_kernel(const float* __restrict__ agg,
                       const float* __restrict__ deg,
                       const float* __restrict__ xb,
                       const float* __restrict__ W,
                       const float* __restrict__ Wl,
                       const float* __restrict__ res_p,
                       const float* __restrict__ jump,
                       const float* __restrict__ jw_p,
                       float* __restrict__ out,
                       int N)
{
    extern __shared__ float sm[];
    float* Ws   = sm;                        // 128x128 row-major
    float* Wls  = sm + 16384;                // 128x128 row-major
    float* xsaT = sm + 32768;                // [128 k][65] transposed (agg/deg)
    float* xsbT = sm + 32768 + 128 * XT_STRIDE;  // [128 k][65] transposed (xb)

    const int t = threadIdx.x;

    // stage both weight matrices
    for (int i = t * 4; i < 16384; i += GEMM_THREADS * 4) {
        *(float4*)(Ws + i)  = *(const float4*)(W + i);
        *(float4*)(Wls + i) = *(const float4*)(Wl + i);
    }
    const float res = __ldg(res_p);
    const float jw  = jump ? __ldg(jw_p) : 0.0f;

    const int cg   = t >> 5;     // 0..15 -> column group
    const int lane = t & 31;     // row within half-tile
    const int cb   = cg * 8;     // 8 output cols per thread

    for (int row0 = blockIdx.x * TILE_ROWS; row0 < N; row0 += gridDim.x * TILE_ROWS) {
        __syncthreads();
        // stage x tiles transposed: element (r, k) -> xsT[k*65 + r]
        for (int i = t * 4; i < TILE_ROWS * D; i += GEMM_THREADS * 4) {
            int r = i >> 7;              // row within tile (const per warp)
            int c = i & 127;             // k base
            int row = row0 + r;
            float4 a, b;
            if (row < N) {
                float inv = 1.0f / fmaxf(__ldg(deg + row), 1.0f);
                a = *(const float4*)(agg + (size_t)row * D + c);
                a.x *= inv; a.y *= inv; a.z *= inv; a.w *= inv;
                b = *(const float4*)(xb + (size_t)row * D + c);
            } else {
                a = make_float4(0.f, 0.f, 0.f, 0.f);
                b = a;
            }
            xsaT[(c + 0) * XT_STRIDE + r] = a.x;
            xsaT[(c + 1) * XT_STRIDE + r] = a.y;
            xsaT[(c + 2) * XT_STRIDE + r] = a.z;
            xsaT[(c + 3) * XT_STRIDE + r] = a.w;
            xsbT[(c + 0) * XT_STRIDE + r] = b.x;
            xsbT[(c + 1) * XT_STRIDE + r] = b.y;
            xsbT[(c + 2) * XT_STRIDE + r] = b.z;
            xsbT[(c + 3) * XT_STRIDE + r] = b.w;
        }
        __syncthreads();

        unsigned long long acc[2][4];
        #pragma unroll
        for (int r = 0; r < 2; r++)
            #pragma unroll
            for (int j = 0; j < 4; j++) acc[r][j] = 0ull;

        #pragma unroll 4
        for (int k = 0; k < D; k++) {
            // weights: all lanes same address -> broadcast, 1 phase per 16B
            ulonglong2 w01 = *(const ulonglong2*)(Ws  + k * D + cb);
            ulonglong2 w23 = *(const ulonglong2*)(Ws  + k * D + cb + 4);
            ulonglong2 l01 = *(const ulonglong2*)(Wls + k * D + cb);
            ulonglong2 l23 = *(const ulonglong2*)(Wls + k * D + cb + 4);
            // x: consecutive per lane -> conflict-free
            unsigned long long A0 = pack_dup(xsaT[k * XT_STRIDE + lane]);
            unsigned long long A1 = pack_dup(xsaT[k * XT_STRIDE + lane + 32]);
            unsigned long long B0 = pack_dup(xsbT[k * XT_STRIDE + lane]);
            unsigned long long B1 = pack_dup(xsbT[k * XT_STRIDE + lane + 32]);
            ffma2(acc[0][0], A0, w01.x); ffma2(acc[0][1], A0, w01.y);
            ffma2(acc[0][2], A0, w23.x); ffma2(acc[0][3], A0, w23.y);
            ffma2(acc[1][0], A1, w01.x); ffma2(acc[1][1], A1, w01.y);
            ffma2(acc[1][2], A1, w23.x); ffma2(acc[1][3], A1, w23.y);
            ffma2(acc[0][0], B0, l01.x); ffma2(acc[0][1], B0, l01.y);
            ffma2(acc[0][2], B0, l23.x); ffma2(acc[0][3], B0, l23.y);
            ffma2(acc[1][0], B1, l01.x); ffma2(acc[1][1], B1, l01.y);
            ffma2(acc[1][2], B1, l23.x); ffma2(acc[1][3], B1, l23.y);
        }

        #pragma unroll
        for (int rr = 0; rr < 2; rr++) {
            int r_in = lane + rr * 32;
            int row = row0 + r_in;
            if (row >= N) continue;
            float o[8];
            #pragma unroll
            for (int j = 0; j < 4; j++)
                unpack2(acc[rr][j], o[2 * j], o[2 * j + 1]);
            #pragma unroll
            for (int j = 0; j < 8; j++) {
                // residual from transposed xb tile: conflict-free (lane-distinct)
                float v = xsbT[(cb + j) * XT_STRIDE + r_in] + res * tanh_fast(o[j]);
                if (jump)
                    v += jw * __ldg(jump + (size_t)row * D + cb + j);
                o[j] = v;
            }
            *(float4*)(out + (size_t)row * D + cb)     = make_float4(o[0], o[1], o[2], o[3]);
            *(float4*)(out + (size_t)row * D + cb + 4) = make_float4(o[4], o[5], o[6], o[7]);
        }
    }
}

// ---------------- launcher ------------------------------------------------
extern "C" void kernel_launch(void* const* d_in, const int* in_sizes, int n_in,
                              void* d_out, int out_size)
{
    const float* emb    = (const float*)d_in[0];
    const float* change = (const float*)d_in[1];
    const float* W1     = (const float*)d_in[2];
    const float* Wl1    = (const float*)d_in[3];
    const float* rel1   = (const float*)d_in[4];
    const float* W2     = (const float*)d_in[5];
    const float* Wl2    = (const float*)d_in[6];
    const float* rel2   = (const float*)d_in[7];
    const float* res    = (const float*)d_in[8];
    const float* jw     = (const float*)d_in[9];
    const float* ewj    = (const float*)d_in[10];
    const int*   ei     = (const int*)d_in[11];
    const int*   et     = (const int*)d_in[12];
    const int*   ej     = (const int*)d_in[13];

    const int N  = in_sizes[0] / D;
    const int E  = in_sizes[12];
    const int EJ = in_sizes[10];

    float* out = (float*)d_out;

    float *agg, *jmp, *h, *deg;
    cudaGetSymbolAddress((void**)&agg, g_agg);
    cudaGetSymbolAddress((void**)&jmp, g_jump);
    cudaGetSymbolAddress((void**)&h,   g_h);
    cudaGetSymbolAddress((void**)&deg, g_deg);

    cudaFuncSetAttribute(gemm_fused_kernel,
                         cudaFuncAttributeMaxDynamicSharedMemorySize, GEMM_SMEM);

    const size_t nd = (size_t)N * D * sizeof(float);

    cudaMemsetAsync(agg, 0, nd);
    cudaMemsetAsync(jmp, 0, nd);
    cudaMemsetAsync(deg, 0, (size_t)N * sizeof(float));

    const int eb = (E + 7) / 8;
    const int jb = (EJ + 7) / 8;
    const int gblocks = 148;

    // layer 1 scatter (+ degree count) and jump scatter (independent)
    scatter_kernel<<<eb, 256>>>(emb, rel1, ei, et, agg, deg, E);
    jump_kernel<<<jb, 256>>>(emb, ewj, ej, jmp, EJ);

    // h = emb + res*tanh((agg/deg)@W1 + emb@Wl1)
    gemm_fused_kernel<<<gblocks, GEMM_THREADS, GEMM_SMEM>>>(
        agg, deg, emb, W1, Wl1, res, nullptr, nullptr, h, N);

    // layer 2 scatter
    cudaMemsetAsync(agg, 0, nd);
    scatter_kernel<<<eb, 256>>>(h, rel2, ei, et, agg, nullptr, E);

    // dchange = h + res*tanh((agg/deg)@W2 + h@Wl2) + jw*jump
    gemm_fused_kernel<<<gblocks, GEMM_THREADS, GEMM_SMEM>>>(
        agg, deg, h, W2, Wl2, res, jmp, jw, out + (size_t)N * D, N);

    // first output: change passthrough
    cudaMemcpyAsync(out, change, nd, cudaMemcpyDeviceToDevice);
}

// round 4
// speedup vs baseline: 1.8056x; 1.1314x over previous
#include <cuda_runtime.h>
#include <cstdint>
#include <cstddef>

#define D 128
#define NMAX 100000

// ---------------- static device scratch (no dynamic allocs allowed) -------
__device__ float g_agg[(size_t)NMAX * D];
__device__ float g_jump[(size_t)NMAX * D];
__device__ float g_h[(size_t)NMAX * D];
__device__ float g_deg[NMAX];

// ---------------- helpers -------------------------------------------------
__device__ __forceinline__ void red4(float* p, float4 v) {
    asm volatile("red.global.add.v4.f32 [%0], {%1,%2,%3,%4};"
                 :: "l"(p), "f"(v.x), "f"(v.y), "f"(v.z), "f"(v.w) : "memory");
}

__device__ __forceinline__ float tanh_fast(float x) {
    float y;
    asm("tanh.approx.f32 %0, %1;" : "=f"(y) : "f"(x));
    return y;
}

__device__ __forceinline__ uint32_t to_tf32(float x) {
    uint32_t r;
    asm("cvt.rna.tf32.f32 %0, %1;" : "=r"(r) : "f"(x));
    return r;
}

// m16n8k8 tf32 mma: C[16x8] += A[16x8] @ B[8x8]
__device__ __forceinline__ void mma_tf32(float* c,
                                         uint32_t a0, uint32_t a1,
                                         uint32_t a2, uint32_t a3,
                                         uint32_t b0, uint32_t b1) {
    asm("mma.sync.aligned.m16n8k8.row.col.f32.tf32.tf32.f32 "
        "{%0,%1,%2,%3}, {%4,%5,%6,%7}, {%8,%9}, {%0,%1,%2,%3};"
        : "+f"(c[0]), "+f"(c[1]), "+f"(c[2]), "+f"(c[3])
        : "r"(a0), "r"(a1), "r"(a2), "r"(a3), "r"(b0), "r"(b1));
}

// ---------------- scatter: agg[dst] += x[src] * rel[etype], deg count -----
__global__ void scatter_kernel(const float* __restrict__ x,
                               const float* __restrict__ rel,
                               const int* __restrict__ ei,     // [2, E]
                               const int* __restrict__ etype,  // [E]
                               float* __restrict__ agg,
                               float* __restrict__ deg,        // null on layer 2
                               int E)
{
    int e = blockIdx.x * (blockDim.x >> 5) + (threadIdx.x >> 5);
    if (e >= E) return;
    int lane = threadIdx.x & 31;
    int s = __ldg(ei + e);
    int d = __ldg(ei + E + e);
    int t = __ldg(etype + e);
    float4 xv = *(const float4*)(x + (size_t)s * D + lane * 4);
    float4 rv = *(const float4*)(rel + (size_t)t * D + lane * 4);
    float4 m;
    m.x = xv.x * rv.x; m.y = xv.y * rv.y;
    m.z = xv.z * rv.z; m.w = xv.w * rv.w;
    red4(agg + (size_t)d * D + lane * 4, m);
    if (deg != nullptr && lane == 0)
        atomicAdd(deg + d, 1.0f);
}

// ---------------- jump: out[jdst] += w[e] * emb[jsrc] ---------------------
__global__ void jump_kernel(const float* __restrict__ emb,
                            const float* __restrict__ ew,
                            const int* __restrict__ ej,   // [2, EJ]
                            float* __restrict__ out,
                            int EJ)
{
    int e = blockIdx.x * (blockDim.x >> 5) + (threadIdx.x >> 5);
    if (e >= EJ) return;
    int lane = threadIdx.x & 31;
    int s = __ldg(ej + e);
    int d = __ldg(ej + EJ + e);
    float w = __ldg(ew + e);
    float4 xv = *(const float4*)(emb + (size_t)s * D + lane * 4);
    float4 m;
    m.x = xv.x * w; m.y = xv.y * w; m.z = xv.z * w; m.w = xv.w * w;
    red4(out + (size_t)d * D + lane * 4, m);
}

// ---------------- tensor-core (mma.sync tf32) fused GEMM + epilogue -------
// out[r] = xb[r] + res * tanh( (agg[r]/max(deg,1)) @ W + xb[r] @ Wl )
//          [ + jw * jump[r]  when jump != null ]
//
// Warp grid 4m x 2n, warp tile 32x64; M_TILE=128 rows per block iteration.
// Weights stored transposed B[n][k] (stride 132) once per block; A tile
// staged per phase (phase0: agg/deg vs W^T, phase1: xb vs Wl^T) into the
// same accumulators.
#define NT 256
#define BSTR 132
#define GEMM_SMEM (3 * 128 * BSTR * 4)   // As + Bw + Bl = 202752 B

__global__ __launch_bounds__(NT, 1)
void gemm_mma_kernel(const float* __restrict__ agg,
                     const float* __restrict__ deg,
                     const float* __restrict__ xb,
                     const float* __restrict__ W,
                     const float* __restrict__ Wl,
                     const float* __restrict__ res_p,
                     const float* __restrict__ jump,
                     const float* __restrict__ jw_p,
                     float* __restrict__ out,
                     int N)
{
    extern __shared__ float sm[];
    float* As = sm;                     // [128 m][132 k]
    float* Bw = sm + 128 * BSTR;        // [128 n][132 k] = W^T (tf32)
    float* Bl = sm + 2 * 128 * BSTR;    // Wl^T (tf32)

    const int t    = threadIdx.x;
    const int lane = t & 31;
    const int wid  = t >> 5;
    const int warp_m = wid & 3;         // 0..3 -> 32-row group
    const int warp_n = wid >> 2;        // 0..1 -> 64-col group

    // ---- stage both weights transposed + tf32-rounded (once) ----
    {
        const int n = t & 127;
        const float* wsrc = (t >> 7) ? Wl : W;
        float* bdst = (t >> 7) ? Bl : Bw;
        #pragma unroll 4
        for (int k = 0; k < 128; k++)
            bdst[n * BSTR + k] = __uint_as_float(to_tf32(__ldg(wsrc + k * 128 + n)));
    }
    const float res = __ldg(res_p);
    const float jw  = jump ? __ldg(jw_p) : 0.0f;
    __syncthreads();

    for (int row0 = blockIdx.x * 128; row0 < N; row0 += gridDim.x * 128) {
        float acc[2][8][4];
        #pragma unroll
        for (int mf = 0; mf < 2; mf++)
            #pragma unroll
            for (int nf = 0; nf < 8; nf++)
                #pragma unroll
                for (int j = 0; j < 4; j++) acc[mf][nf][j] = 0.0f;

        #pragma unroll 1
        for (int phase = 0; phase < 2; phase++) {
            __syncthreads();   // previous readers of As done
            // ---- stage A tile (tf32) ----
            for (int i = t * 4; i < 128 * 128; i += NT * 4) {
                int m = i >> 7, k = i & 127;
                int row = row0 + m;
                float4 v = make_float4(0.f, 0.f, 0.f, 0.f);
                if (row < N) {
                    if (phase == 0) {
                        float inv = 1.0f / fmaxf(__ldg(deg + row), 1.0f);
                        v = *(const float4*)(agg + (size_t)row * D + k);
                        v.x *= inv; v.y *= inv; v.z *= inv; v.w *= inv;
                    } else {
                        v = *(const float4*)(xb + (size_t)row * D + k);
                    }
                }
                uint4 u;
                u.x = to_tf32(v.x); u.y = to_tf32(v.y);
                u.z = to_tf32(v.z); u.w = to_tf32(v.w);
                *(uint4*)(As + m * BSTR + k) = u;
            }
            __syncthreads();

            const float* Bsel = phase ? Bl : Bw;
            const int arow = warp_m * 32 + (lane >> 2);
            const int nrow = warp_n * 64 + (lane >> 2);

            #pragma unroll
            for (int ks = 0; ks < 16; ks++) {
                uint32_t a[2][4];
                const int ab = arow * BSTR + ks * 8 + (lane & 3);
                #pragma unroll
                for (int mf = 0; mf < 2; mf++) {
                    int p = ab + mf * 16 * BSTR;
                    a[mf][0] = __float_as_uint(As[p]);
                    a[mf][1] = __float_as_uint(As[p + 8 * BSTR]);
                    a[mf][2] = __float_as_uint(As[p + 4]);
                    a[mf][3] = __float_as_uint(As[p + 8 * BSTR + 4]);
                }
                #pragma unroll
                for (int nf = 0; nf < 8; nf++) {
                    int nb = (nrow + nf * 8) * BSTR + ks * 8 + (lane & 3);
                    uint32_t b0 = __float_as_uint(Bsel[nb]);
                    uint32_t b1 = __float_as_uint(Bsel[nb + 4]);
                    mma_tf32(acc[0][nf], a[0][0], a[0][1], a[0][2], a[0][3], b0, b1);
                    mma_tf32(acc[1][nf], a[1][0], a[1][1], a[1][2], a[1][3], b0, b1);
                }
            }
        }

        // ---- epilogue: res*tanh + residual + jump, straight from frags ----
        #pragma unroll
        for (int mf = 0; mf < 2; mf++) {
            #pragma unroll
            for (int half = 0; half < 2; half++) {
                int row = row0 + warp_m * 32 + mf * 16 + half * 8 + (lane >> 2);
                if (row >= N) continue;
                #pragma unroll
                for (int nf = 0; nf < 8; nf++) {
                    int col = warp_n * 64 + nf * 8 + 2 * (lane & 3);
                    float v0 = acc[mf][nf][half * 2 + 0];
                    float v1 = acc[mf][nf][half * 2 + 1];
                    float2 b = *(const float2*)(xb + (size_t)row * D + col);
                    v0 = b.x + res * tanh_fast(v0);
                    v1 = b.y + res * tanh_fast(v1);
                    if (jump) {
                        float2 jv = *(const float2*)(jump + (size_t)row * D + col);
                        v0 += jw * jv.x;
                        v1 += jw * jv.y;
                    }
                    float2 o; o.x = v0; o.y = v1;
                    *(float2*)(out + (size_t)row * D + col) = o;
                }
            }
        }
    }
}

// ---------------- launcher ------------------------------------------------
extern "C" void kernel_launch(void* const* d_in, const int* in_sizes, int n_in,
                              void* d_out, int out_size)
{
    const float* emb    = (const float*)d_in[0];
    const float* change = (const float*)d_in[1];
    const float* W1     = (const float*)d_in[2];
    const float* Wl1    = (const float*)d_in[3];
    const float* rel1   = (const float*)d_in[4];
    const float* W2     = (const float*)d_in[5];
    const float* Wl2    = (const float*)d_in[6];
    const float* rel2   = (const float*)d_in[7];
    const float* res    = (const float*)d_in[8];
    const float* jw     = (const float*)d_in[9];
    const float* ewj    = (const float*)d_in[10];
    const int*   ei     = (const int*)d_in[11];
    const int*   et     = (const int*)d_in[12];
    const int*   ej     = (const int*)d_in[13];

    const int N  = in_sizes[0] / D;
    const int E  = in_sizes[12];
    const int EJ = in_sizes[10];

    float* out = (float*)d_out;

    float *agg, *jmp, *h, *deg;
    cudaGetSymbolAddress((void**)&agg, g_agg);
    cudaGetSymbolAddress((void**)&jmp, g_jump);
    cudaGetSymbolAddress((void**)&h,   g_h);
    cudaGetSymbolAddress((void**)&deg, g_deg);

    cudaFuncSetAttribute(gemm_mma_kernel,
                         cudaFuncAttributeMaxDynamicSharedMemorySize, GEMM_SMEM);

    const size_t nd = (size_t)N * D * sizeof(float);

    cudaMemsetAsync(agg, 0, nd);
    cudaMemsetAsync(jmp, 0, nd);
    cudaMemsetAsync(deg, 0, (size_t)N * sizeof(float));

    const int eb = (E + 7) / 8;
    const int jb = (EJ + 7) / 8;

    // layer 1 scatter (+ degree count) and jump scatter (independent)
    scatter_kernel<<<eb, 256>>>(emb, rel1, ei, et, agg, deg, E);
    jump_kernel<<<jb, 256>>>(emb, ewj, ej, jmp, EJ);

    // h = emb + res*tanh((agg/deg)@W1 + emb@Wl1)
    gemm_mma_kernel<<<148, NT, GEMM_SMEM>>>(
        agg, deg, emb, W1, Wl1, res, nullptr, nullptr, h, N);

    // layer 2 scatter
    cudaMemsetAsync(agg, 0, nd);
    scatter_kernel<<<eb, 256>>>(h, rel2, ei, et, agg, nullptr, E);

    // dchange = h + res*tanh((agg/deg)@W2 + h@Wl2) + jw*jump
    gemm_mma_kernel<<<148, NT, GEMM_SMEM>>>(
        agg, deg, h, W2, Wl2, res, jmp, jw, out + (size_t)N * D, N);

    // first output: change passthrough
    cudaMemcpyAsync(out, change, nd, cudaMemcpyDeviceToDevice);
}

// round 5
// speedup vs baseline: 2.4950x; 1.3818x over previous
#include <cuda_runtime.h>
#include <cstdint>
#include <cstddef>

#define D 128
#define NMAX 100000

// ---------------- static device scratch (no dynamic allocs allowed) -------
__device__ float g_agg[(size_t)NMAX * D];
__device__ float g_jump[(size_t)NMAX * D];
__device__ float g_h[(size_t)NMAX * D];
__device__ float g_deg[NMAX];

// ---------------- helpers -------------------------------------------------
__device__ __forceinline__ void red4(float* p, float4 v) {
    asm volatile("red.global.add.v4.f32 [%0], {%1,%2,%3,%4};"
                 :: "l"(p), "f"(v.x), "f"(v.y), "f"(v.z), "f"(v.w) : "memory");
}

__device__ __forceinline__ float tanh_fast(float x) {
    float y;
    asm("tanh.approx.f32 %0, %1;" : "=f"(y) : "f"(x));
    return y;
}

// pack two f32 -> bf16x2 (lo = first/lower-k element, hi = second)
__device__ __forceinline__ uint32_t bf16x2(float lo, float hi) {
    uint32_t r;
    asm("cvt.rn.bf16x2.f32 %0, %1, %2;" : "=r"(r) : "f"(hi), "f"(lo));
    return r;
}

// m16n8k16 bf16 mma: C[16x8] += A[16x16] @ B[16x8]
__device__ __forceinline__ void mma_bf16(float* c,
                                         uint32_t a0, uint32_t a1,
                                         uint32_t a2, uint32_t a3,
                                         uint32_t b0, uint32_t b1) {
    asm("mma.sync.aligned.m16n8k16.row.col.f32.bf16.bf16.f32 "
        "{%0,%1,%2,%3}, {%4,%5,%6,%7}, {%8,%9}, {%0,%1,%2,%3};"
        : "+f"(c[0]), "+f"(c[1]), "+f"(c[2]), "+f"(c[3])
        : "r"(a0), "r"(a1), "r"(a2), "r"(a3), "r"(b0), "r"(b1));
}

// Permuted-k bf16 row store. Row layout (per 16-k block, 32 bytes):
// logical k -> pos = ((k&7)>>1)*2pairs... storage order [0,1,8,9,2,3,10,11,4,5,12,13,6,7,14,15]
// so that one uint2 (8B) load at offset (lane&3)*8 yields {k,k+1} and {k+8,k+9}.
// Valid for k % 4 == 0: writes pairs (k,k+1) and (k+2,k+3).
__device__ __forceinline__ void store_bf16_quad(char* rowbase, int k, float4 v) {
    char* p = rowbase + ((k >> 4) * 32) + (((k & 7) >> 1) * 8) + (((k >> 3) & 1) * 4);
    *(uint32_t*)p       = bf16x2(v.x, v.y);
    *(uint32_t*)(p + 8) = bf16x2(v.z, v.w);
}

// ---------------- scatter: agg[dst] += x[src] * rel[etype], deg count -----
__global__ void scatter_kernel(const float* __restrict__ x,
                               const float* __restrict__ rel,
                               const int* __restrict__ ei,     // [2, E]
                               const int* __restrict__ etype,  // [E]
                               float* __restrict__ agg,
                               float* __restrict__ deg,        // null on layer 2
                               int E)
{
    int e = blockIdx.x * (blockDim.x >> 5) + (threadIdx.x >> 5);
    if (e >= E) return;
    int lane = threadIdx.x & 31;
    int s = __ldg(ei + e);
    int d = __ldg(ei + E + e);
    int t = __ldg(etype + e);
    float4 xv = *(const float4*)(x + (size_t)s * D + lane * 4);
    float4 rv = *(const float4*)(rel + (size_t)t * D + lane * 4);
    float4 m;
    m.x = xv.x * rv.x; m.y = xv.y * rv.y;
    m.z = xv.z * rv.z; m.w = xv.w * rv.w;
    red4(agg + (size_t)d * D + lane * 4, m);
    if (deg != nullptr && lane == 0)
        atomicAdd(deg + d, 1.0f);
}

// ---------------- jump: out[jdst] += w[e] * emb[jsrc] ---------------------
__global__ void jump_kernel(const float* __restrict__ emb,
                            const float* __restrict__ ew,
                            const int* __restrict__ ej,   // [2, EJ]
                            float* __restrict__ out,
                            int EJ)
{
    int e = blockIdx.x * (blockDim.x >> 5) + (threadIdx.x >> 5);
    if (e >= EJ) return;
    int lane = threadIdx.x & 31;
    int s = __ldg(ej + e);
    int d = __ldg(ej + EJ + e);
    float w = __ldg(ew + e);
    float4 xv = *(const float4*)(emb + (size_t)s * D + lane * 4);
    float4 m;
    m.x = xv.x * w; m.y = xv.y * w; m.z = xv.z * w; m.w = xv.w * w;
    red4(out + (size_t)d * D + lane * 4, m);
}

// ---------------- tensor-core (mma.sync bf16) fused GEMM + epilogue -------
// out[r] = xb[r] + res * tanh( (agg[r]/max(deg,1)) @ W + xb[r] @ Wl )
//          [ + jw * jump[r]  when jump != null ]
//
// Warp grid 4m x 2n, warp tile 32x64, M_TILE=128. K=16 per mma step.
// A/B in bf16 smem with permuted-k layout -> all fragment loads are LDS.64,
// conflict-free (row stride 288B). 108KB smem -> 2 CTAs/SM (16 warps).
#define NT 256
#define RSTR 288                      // bytes per 128-k row (256 + 32 pad)
#define SM_A  0
#define SM_BW (128 * RSTR)            // 36864
#define SM_BL (2 * 128 * RSTR)        // 73728
#define GEMM_SMEM (3 * 128 * RSTR)    // 110592 B

__global__ __launch_bounds__(NT, 2)
void gemm_mma_kernel(const float* __restrict__ agg,
                     const float* __restrict__ deg,
                     const float* __restrict__ xb,
                     const float* __restrict__ W,
                     const float* __restrict__ Wl,
                     const float* __restrict__ res_p,
                     const float* __restrict__ jump,
                     const float* __restrict__ jw_p,
                     float* __restrict__ out,
                     int N)
{
    extern __shared__ char smem[];
    char* As = smem + SM_A;          // [128 m][RSTR]  A tile (bf16, perm-k)
    char* Bw = smem + SM_BW;         // [128 n][RSTR]  W^T  (bf16, perm-k)
    char* Bl = smem + SM_BL;         // [128 n][RSTR]  Wl^T (bf16, perm-k)

    const int t    = threadIdx.x;
    const int lane = t & 31;
    const int wid  = t >> 5;
    const int warp_m = wid & 3;      // 0..3 -> 32-row group
    const int warp_n = wid >> 2;     // 0..1 -> 64-col group

    // ---- stage both weights transposed into perm-k bf16 layout (once) ----
    // thread owns column n = t&127 of W or Wl; reads coalesced along n.
    {
        const int n = t & 127;
        const float* wsrc = (t >> 7) ? Wl : W;
        char* brow = ((t >> 7) ? Bl : Bw) + n * RSTR;
        #pragma unroll 4
        for (int k = 0; k < 128; k += 4) {
            float4 v;
            v.x = __ldg(wsrc + (k + 0) * 128 + n);
            v.y = __ldg(wsrc + (k + 1) * 128 + n);
            v.z = __ldg(wsrc + (k + 2) * 128 + n);
            v.w = __ldg(wsrc + (k + 3) * 128 + n);
            store_bf16_quad(brow, k, v);
        }
    }
    const float res = __ldg(res_p);
    const float jw  = jump ? __ldg(jw_p) : 0.0f;
    __syncthreads();

    for (int row0 = blockIdx.x * 128; row0 < N; row0 += gridDim.x * 128) {
        float acc[2][8][4];
        #pragma unroll
        for (int mf = 0; mf < 2; mf++)
            #pragma unroll
            for (int nf = 0; nf < 8; nf++)
                #pragma unroll
                for (int j = 0; j < 4; j++) acc[mf][nf][j] = 0.0f;

        #pragma unroll 1
        for (int phase = 0; phase < 2; phase++) {
            __syncthreads();   // previous readers of As done
            // ---- stage A tile (bf16, perm-k) ----
            for (int i = t * 4; i < 128 * 128; i += NT * 4) {
                int m = i >> 7, k = i & 127;
                int row = row0 + m;
                float4 v = make_float4(0.f, 0.f, 0.f, 0.f);
                if (row < N) {
                    if (phase == 0) {
                        float inv = 1.0f / fmaxf(__ldg(deg + row), 1.0f);
                        v = *(const float4*)(agg + (size_t)row * D + k);
                        v.x *= inv; v.y *= inv; v.z *= inv; v.w *= inv;
                    } else {
                        v = *(const float4*)(xb + (size_t)row * D + k);
                    }
                }
                store_bf16_quad(As + m * RSTR, k, v);
            }
            __syncthreads();

            const char* Bsel = phase ? Bl : Bw;
            const int a_base = (warp_m * 32 + (lane >> 2)) * RSTR + (lane & 3) * 8;
            const int b_base = (warp_n * 64 + (lane >> 2)) * RSTR + (lane & 3) * 8;

            #pragma unroll
            for (int ks = 0; ks < 8; ks++) {
                // A fragments: one LDS.64 per (mf, row-half)
                uint2 a_f[2][2];
                #pragma unroll
                for (int mf = 0; mf < 2; mf++) {
                    const char* ap = As + a_base + mf * 16 * RSTR + ks * 32;
                    a_f[mf][0] = *(const uint2*)ap;                 // {a0, a2} row r
                    a_f[mf][1] = *(const uint2*)(ap + 8 * RSTR);    // {a1, a3} row r+8
                }
                #pragma unroll
                for (int nf = 0; nf < 8; nf++) {
                    uint2 b = *(const uint2*)(Bsel + b_base + nf * 8 * RSTR + ks * 32);
                    mma_bf16(acc[0][nf], a_f[0][0].x, a_f[0][1].x,
                             a_f[0][0].y, a_f[0][1].y, b.x, b.y);
                    mma_bf16(acc[1][nf], a_f[1][0].x, a_f[1][1].x,
                             a_f[1][0].y, a_f[1][1].y, b.x, b.y);
                }
            }
        }

        // ---- epilogue: res*tanh + residual + jump, straight from frags ----
        #pragma unroll
        for (int mf = 0; mf < 2; mf++) {
            #pragma unroll
            for (int half = 0; half < 2; half++) {
                int row = row0 + warp_m * 32 + mf * 16 + half * 8 + (lane >> 2);
                if (row >= N) continue;
                #pragma unroll
                for (int nf = 0; nf < 8; nf++) {
                    int col = warp_n * 64 + nf * 8 + 2 * (lane & 3);
                    float v0 = acc[mf][nf][half * 2 + 0];
                    float v1 = acc[mf][nf][half * 2 + 1];
                    float2 b = *(const float2*)(xb + (size_t)row * D + col);
                    v0 = b.x + res * tanh_fast(v0);
                    v1 = b.y + res * tanh_fast(v1);
                    if (jump) {
                        float2 jv = *(const float2*)(jump + (size_t)row * D + col);
                        v0 += jw * jv.x;
                        v1 += jw * jv.y;
                    }
                    float2 o; o.x = v0; o.y = v1;
                    *(float2*)(out + (size_t)row * D + col) = o;
                }
            }
        }
    }
}

// ---------------- launcher ------------------------------------------------
extern "C" void kernel_launch(void* const* d_in, const int* in_sizes, int n_in,
                              void* d_out, int out_size)
{
    const float* emb    = (const float*)d_in[0];
    const float* change = (const float*)d_in[1];
    const float* W1     = (const float*)d_in[2];
    const float* Wl1    = (const float*)d_in[3];
    const float* rel1   = (const float*)d_in[4];
    const float* W2     = (const float*)d_in[5];
    const float* Wl2    = (const float*)d_in[6];
    const float* rel2   = (const float*)d_in[7];
    const float* res    = (const float*)d_in[8];
    const float* jw     = (const float*)d_in[9];
    const float* ewj    = (const float*)d_in[10];
    const int*   ei     = (const int*)d_in[11];
    const int*   et     = (const int*)d_in[12];
    const int*   ej     = (const int*)d_in[13];

    const int N  = in_sizes[0] / D;
    const int E  = in_sizes[12];
    const int EJ = in_sizes[10];

    float* out = (float*)d_out;

    float *agg, *jmp, *h, *deg;
    cudaGetSymbolAddress((void**)&agg, g_agg);
    cudaGetSymbolAddress((void**)&jmp, g_jump);
    cudaGetSymbolAddress((void**)&h,   g_h);
    cudaGetSymbolAddress((void**)&deg, g_deg);

    cudaFuncSetAttribute(gemm_mma_kernel,
                         cudaFuncAttributeMaxDynamicSharedMemorySize, GEMM_SMEM);

    const size_t nd = (size_t)N * D * sizeof(float);

    cudaMemsetAsync(agg, 0, nd);
    cudaMemsetAsync(jmp, 0, nd);
    cudaMemsetAsync(deg, 0, (size_t)N * sizeof(float));

    const int eb = (E + 7) / 8;
    const int jb = (EJ + 7) / 8;

    // layer 1 scatter (+ degree count) and jump scatter (independent)
    scatter_kernel<<<eb, 256>>>(emb, rel1, ei, et, agg, deg, E);
    jump_kernel<<<jb, 256>>>(emb, ewj, ej, jmp, EJ);

    // h = emb + res*tanh((agg/deg)@W1 + emb@Wl1)
    gemm_mma_kernel<<<296, NT, GEMM_SMEM>>>(
        agg, deg, emb, W1, Wl1, res, nullptr, nullptr, h, N);

    // layer 2 scatter
    cudaMemsetAsync(agg, 0, nd);
    scatter_kernel<<<eb, 256>>>(h, rel2, ei, et, agg, nullptr, E);

    // dchange = h + res*tanh((agg/deg)@W2 + h@Wl2) + jw*jump
    gemm_mma_kernel<<<296, NT, GEMM_SMEM>>>(
        agg, deg, h, W2, Wl2, res, jmp, jw, out + (size_t)N * D, N);

    // first output: change passthrough
    cudaMemcpyAsync(out, change, nd, cudaMemcpyDeviceToDevice);
}